// round 10
// baseline (speedup 1.0000x reference)
#include <cuda_runtime.h>
#include <math.h>

#define NN 50000
#define CC 256
#define EE 800000
#define HH 64
#define KK 32
#define LL 2
#define NB 64   // nodes per block in tiled node kernels

typedef unsigned long long ull;

// ---- scratch (no allocation allowed) ----
__device__ float g_ah[NN * 128];   // per node: [0:64) gate-a proj, [64:128) h
__device__ float g_m[NN * HH];     // scatter accumulator (zero-invariant between replays)
__device__ float g_deg[NN];        // weighted degree (zero-invariant between replays)
__device__ float g_rho[NN];        // sigmoid(rho_raw)
__device__ float g_b[NN * HH];     // per-node dst-side gate projection
__device__ float g_w0[EE];         // base_w * rho[src] * rho[dst]
__device__ int   g_soff[EE];       // src * 128  (element offset into g_ah)
__device__ int   g_doff[EE];       // dst * 64   (element offset into g_b / g_m)

// dynamic smem layout (floats): sWd[64][128] | sA[64][68] | sInv[64]
#define SWD_FLOATS (64 * 128)
#define SA_FLOATS  (64 * 68)
#define DSM_BYTES  ((SWD_FLOATS + SA_FLOATS + 64) * 4)

// packed dual fp32 FMA: d.lo += a.lo*b.lo ; d.hi += a.hi*b.hi  (IEEE fp32 each)
__device__ __forceinline__ void fma2(ull& d, ull a, ull b) {
    asm("fma.rn.f32x2 %0, %1, %2, %0;" : "+l"(d) : "l"(a), "l"(b));
}

__device__ __forceinline__ void zero8(ull* a) {
#pragma unroll
    for (int k = 0; k < 8; k++) a[k] = 0ull;
}

__device__ __forceinline__ void red_v4(float* addr, float4 v) {
    asm volatile("red.global.add.v4.f32 [%0], {%1, %2, %3, %4};"
                 :: "l"(addr), "f"(v.x), "f"(v.y), "f"(v.z), "f"(v.w) : "memory");
}

// stage 64x64 row-major W into sWd with each weight duplicated: (w,w) pairs
#define STAGE_WD(sWd, gptr) do {                                          \
    _Pragma("unroll")                                                     \
    for (int _q = 0; _q < 4; _q++) {                                      \
        int _lin = _q * 256 + tid;                                        \
        float4 _w = *(const float4*)&(gptr)[_lin * 4];                    \
        int _r = _lin >> 4, _c = (_lin & 15) * 8;                         \
        *(float4*)&sWd[_r][_c]     = make_float4(_w.x, _w.x, _w.y, _w.y); \
        *(float4*)&sWd[_r][_c + 4] = make_float4(_w.z, _w.z, _w.w, _w.w); \
    }                                                                     \
} while (0)

// packed tiled matvec: acc2[p*4+c] = packed (node ng*4+2p, ng*4+2p+1), ch cg*4+c
#define MATVEC_X2(sA, sWd, acc2) do {                                     \
    _Pragma("unroll 8")                                                   \
    for (int _i = 0; _i < 64; _i++) {                                     \
        ulonglong2 _a2  = *(ulonglong2*)&sA[_i][ng * 4];                  \
        ulonglong2 _w01 = *(ulonglong2*)&sWd[_i][cg * 8];                 \
        ulonglong2 _w23 = *(ulonglong2*)&sWd[_i][cg * 8 + 4];             \
        fma2(acc2[0], _a2.x, _w01.x); fma2(acc2[1], _a2.x, _w01.y);       \
        fma2(acc2[2], _a2.x, _w23.x); fma2(acc2[3], _a2.x, _w23.y);       \
        fma2(acc2[4], _a2.y, _w01.x); fma2(acc2[5], _a2.y, _w01.y);       \
        fma2(acc2[6], _a2.y, _w23.x); fma2(acc2[7], _a2.y, _w23.y);       \
    }                                                                     \
} while (0)

// unpack packed accumulators into acc[n*4+c] (n local 0..3)
#define UNPACK_ACC(acc2, acc) do {                                        \
    _Pragma("unroll")                                                     \
    for (int _p = 0; _p < 2; _p++) {                                      \
        _Pragma("unroll")                                                 \
        for (int _c = 0; _c < 4; _c++) {                                  \
            float _lo, _hi;                                               \
            asm("mov.b64 {%0, %1}, %2;"                                   \
                : "=f"(_lo), "=f"(_hi) : "l"((acc2)[_p * 4 + _c]));       \
            acc[(2 * _p) * 4 + _c]     = _lo;                             \
            acc[(2 * _p + 1) * 4 + _c] = _hi;                             \
        }                                                                 \
    }                                                                     \
} while (0)

// =====================================================================
// Encoder (tiled, f32x2): h = relu(relu(x@W1+b1)@W2+b2); fused gate
// projections a -> g_ah[:,0:64], h -> g_ah[:,64:128], b -> g_b.
// =====================================================================
__global__ void __launch_bounds__(256) k_encoder(
        const float* __restrict__ x,
        const float* __restrict__ w1, const float* __restrict__ b1,
        const float* __restrict__ w2, const float* __restrict__ b2,
        const float* __restrict__ gw1, const float* __restrict__ gb1) {
    extern __shared__ float dsm[];
    float (*sWd)[128] = (float(*)[128])dsm;
    float (*sA)[68]   = (float(*)[68])(dsm + SWD_FLOATS);
    int tid = threadIdx.x;
    int cg = tid & 15, ng = tid >> 4;
    int n0 = blockIdx.x * NB;

    ull acc2[8];
    float acc[16];
    zero8(acc2);

    // ---- layer1: K=256 in 4 chunks of 64 ----
    for (int kb = 0; kb < 4; kb++) {
#pragma unroll
        for (int q = 0; q < 4; q++) {
            int lin = q * 256 + tid;
            int node = lin >> 4;
            int c4 = (lin & 15) * 4;
            int n = n0 + node;
            float4 v = make_float4(0.f, 0.f, 0.f, 0.f);
            if (n < NN) v = *(const float4*)&x[(size_t)n * CC + kb * 64 + c4];
            sA[c4 + 0][node] = v.x; sA[c4 + 1][node] = v.y;
            sA[c4 + 2][node] = v.z; sA[c4 + 3][node] = v.w;
        }
        STAGE_WD(sWd, w1 + (size_t)kb * 64 * HH);
        __syncthreads();
        MATVEC_X2(sA, sWd, acc2);
        __syncthreads();
    }
    UNPACK_ACC(acc2, acc);

    // h1 = relu(acc + b1); write transposed into sA, stage w2
    {
        float4 bv = *(const float4*)&b1[cg * 4];
        float bb[4] = {bv.x, bv.y, bv.z, bv.w};
#pragma unroll
        for (int n = 0; n < 4; n++)
#pragma unroll
            for (int c = 0; c < 4; c++)
                sA[cg * 4 + c][ng * 4 + n] = fmaxf(acc[n * 4 + c] + bb[c], 0.f);
    }
    STAGE_WD(sWd, w2);
    __syncthreads();

    zero8(acc2);
    MATVEC_X2(sA, sWd, acc2);
    UNPACK_ACC(acc2, acc);
    __syncthreads();

    // h = relu(acc + b2); store to g_ah[:,64:], write transposed into sA
    float hval[16];
    {
        float4 bv = *(const float4*)&b2[cg * 4];
        float bb[4] = {bv.x, bv.y, bv.z, bv.w};
#pragma unroll
        for (int n = 0; n < 4; n++) {
            int node = n0 + ng * 4 + n;
#pragma unroll
            for (int c = 0; c < 4; c++) {
                hval[n * 4 + c] = fmaxf(acc[n * 4 + c] + bb[c], 0.f);
                sA[cg * 4 + c][ng * 4 + n] = hval[n * 4 + c];
            }
            if (node < NN)
                *(float4*)&g_ah[(size_t)node * 128 + 64 + cg * 4] =
                    make_float4(hval[n*4], hval[n*4+1], hval[n*4+2], hval[n*4+3]);
        }
    }
    STAGE_WD(sWd, gw1);                 // first 64 rows of gate W1
    __syncthreads();

    zero8(acc2);
    MATVEC_X2(sA, sWd, acc2);
    UNPACK_ACC(acc2, acc);
#pragma unroll
    for (int n = 0; n < 4; n++) {
        int node = n0 + ng * 4 + n;
        if (node < NN)
            *(float4*)&g_ah[(size_t)node * 128 + cg * 4] =
                make_float4(acc[n*4], acc[n*4+1], acc[n*4+2], acc[n*4+3]);
    }
    __syncthreads();
    STAGE_WD(sWd, gw1 + (size_t)64 * HH);  // second 64 rows
    __syncthreads();

    zero8(acc2);
    MATVEC_X2(sA, sWd, acc2);
    UNPACK_ACC(acc2, acc);
    {
        float4 bv = *(const float4*)&gb1[cg * 4];
        float bb[4] = {bv.x, bv.y, bv.z, bv.w};
#pragma unroll
        for (int n = 0; n < 4; n++) {
            int node = n0 + ng * 4 + n;
            if (node < NN)
                *(float4*)&g_b[(size_t)node * HH + cg * 4] =
                    make_float4(acc[n*4] + bb[0], acc[n*4+1] + bb[1],
                                acc[n*4+2] + bb[2], acc[n*4+3] + bb[3]);
        }
    }
}

// =====================================================================
__global__ void k_rho(const float* __restrict__ rho_raw) {
    int i = blockIdx.x * blockDim.x + threadIdx.x;
    if (i < NN) g_rho[i] = 1.f / (1.f + __expf(-rho_raw[i]));
}

__global__ void k_w0(const int* __restrict__ src, const int* __restrict__ dst,
                     const float* __restrict__ basew) {
    int i = blockIdx.x * blockDim.x + threadIdx.x;
    if (i < EE) {
        int s = src[i], d = dst[i];
        g_w0[i] = basew[i] * g_rho[s] * g_rho[d];
        g_soff[i] = s * 128;
        g_doff[i] = d * 64;
    }
}

// =====================================================================
// Edge kernel: half-warp per edge; lane owns 4 channels. grid = EE/32.
// =====================================================================
__global__ void __launch_bounds__(256) k_edge(
        const float* __restrict__ gw2, const float* __restrict__ gb2) {
    __shared__ float4 sw2[16];
    __shared__ float sb2;
    int tid = threadIdx.x;
    if (tid < 16) sw2[tid] = *(const float4*)&gw2[tid * 4];
    if (tid == 0) sb2 = gb2[0];
    __syncthreads();

    int lane = tid & 31;
    int warp = tid >> 5;
    int sub = lane >> 4;
    int sl  = lane & 15;
    int e0 = (blockIdx.x * 8 + warp) * 4;

    int4 so4 = *(const int4*)&g_soff[e0];
    int4 do4 = *(const int4*)&g_doff[e0];
    float4 w04 = *(const float4*)&g_w0[e0];
    int soE[4] = {so4.x, so4.y, so4.z, so4.w};
    int doE[4] = {do4.x, do4.y, do4.z, do4.w};
    float w0E[4] = {w04.x, w04.y, w04.z, w04.w};

    float4 w2v = sw2[sl];
    float b2v = sb2;

    int doI[2];
    float4 av[2], bv[2], hv[2];
    float w0I[2];
#pragma unroll
    for (int t = 0; t < 2; t++) {
        int ei = t * 2 + sub;
        doI[t] = doE[ei]; w0I[t] = w0E[ei];
        const float* ahp = g_ah + soE[ei] + sl * 4;
        av[t] = *(const float4*)ahp;
        hv[t] = *(const float4*)(ahp + 64);
        bv[t] = *(const float4*)(g_b + doI[t] + sl * 4);
    }

    float part[2];
#pragma unroll
    for (int t = 0; t < 2; t++)
        part[t] = fmaxf(av[t].x + bv[t].x, 0.f) * w2v.x
                + fmaxf(av[t].y + bv[t].y, 0.f) * w2v.y
                + fmaxf(av[t].z + bv[t].z, 0.f) * w2v.z
                + fmaxf(av[t].w + bv[t].w, 0.f) * w2v.w;

#pragma unroll
    for (int off = 8; off; off >>= 1) {
        part[0] += __shfl_xor_sync(0xffffffffu, part[0], off);
        part[1] += __shfl_xor_sync(0xffffffffu, part[1], off);
    }

#pragma unroll
    for (int t = 0; t < 2; t++) {
        float gate = 1.f / (1.f + __expf(-(part[t] + b2v)));
        float wt = w0I[t] * gate;
        float4 mv = make_float4(wt * hv[t].x, wt * hv[t].y,
                                wt * hv[t].z, wt * hv[t].w);
        red_v4(&g_m[doI[t] + sl * 4], mv);
        if (sl == 0) atomicAdd(&g_deg[doI[t] >> 6], wt);
    }
}

// =====================================================================
// Node update (tiled, f32x2) + LayerNorm + gate projections (mode=1)
// or fused output head (mode=0). Resets g_m/g_deg (replay invariant).
// =====================================================================
__global__ void __launch_bounds__(256) k_update(
        const float* __restrict__ uw1, const float* __restrict__ ub1,
        const float* __restrict__ uw2, const float* __restrict__ ub2,
        const float* __restrict__ lng, const float* __restrict__ lnb,
        const float* __restrict__ gw1, const float* __restrict__ gb1,
        const float* __restrict__ tw, const float* __restrict__ tb,
        float* __restrict__ out, int mode) {
    extern __shared__ float dsm[];
    float (*sWd)[128] = (float(*)[128])dsm;
    float (*sA)[68]   = (float(*)[68])(dsm + SWD_FLOATS);
    float *sInv       = dsm + SWD_FLOATS + SA_FLOATS;
    int tid = threadIdx.x;
    int cg = tid & 15, ng = tid >> 4;
    int n0 = blockIdx.x * NB;

    if (tid < NB) {
        int n = n0 + tid;
        float deg = (n < NN) ? g_deg[n] : 0.f;
        sInv[tid] = 1.f / (deg + 1e-8f);
        if (n < NN) g_deg[n] = 0.f;
    }
    __syncthreads();

    // stage neigh = m*inv transposed; reset g_m; stage uw1
#pragma unroll
    for (int q = 0; q < 4; q++) {
        int lin = q * 256 + tid;
        int node = lin >> 4;
        int c4 = (lin & 15) * 4;
        int n = n0 + node;
        float4 v = make_float4(0.f, 0.f, 0.f, 0.f);
        if (n < NN) {
            v = *(const float4*)&g_m[(size_t)n * HH + c4];
            *(float4*)&g_m[(size_t)n * HH + c4] = make_float4(0.f, 0.f, 0.f, 0.f);
        }
        float inv = sInv[node];
        sA[c4 + 0][node] = v.x * inv; sA[c4 + 1][node] = v.y * inv;
        sA[c4 + 2][node] = v.z * inv; sA[c4 + 3][node] = v.w * inv;
    }
    STAGE_WD(sWd, uw1);
    __syncthreads();

    ull acc2[8];
    float acc[16];
    zero8(acc2);
    MATVEC_X2(sA, sWd, acc2);
    UNPACK_ACC(acc2, acc);
    __syncthreads();

    // t = relu(acc + ub1) -> transposed into sA; stage uw2
    {
        float4 bv = *(const float4*)&ub1[cg * 4];
        float bb[4] = {bv.x, bv.y, bv.z, bv.w};
#pragma unroll
        for (int n = 0; n < 4; n++)
#pragma unroll
            for (int c = 0; c < 4; c++)
                sA[cg * 4 + c][ng * 4 + n] = fmaxf(acc[n * 4 + c] + bb[c], 0.f);
    }
    STAGE_WD(sWd, uw2);
    __syncthreads();

    zero8(acc2);
    MATVEC_X2(sA, sWd, acc2);
    UNPACK_ACC(acc2, acc);

    // pre = h + u; LayerNorm per node
    float pre[16];
    {
        float4 bv = *(const float4*)&ub2[cg * 4];
        float bb[4] = {bv.x, bv.y, bv.z, bv.w};
#pragma unroll
        for (int n = 0; n < 4; n++) {
            int node = n0 + ng * 4 + n;
            float4 h4 = make_float4(0.f, 0.f, 0.f, 0.f);
            if (node < NN)
                h4 = *(const float4*)&g_ah[(size_t)node * 128 + 64 + cg * 4];
            pre[n * 4 + 0] = h4.x + acc[n * 4 + 0] + bb[0];
            pre[n * 4 + 1] = h4.y + acc[n * 4 + 1] + bb[1];
            pre[n * 4 + 2] = h4.z + acc[n * 4 + 2] + bb[2];
            pre[n * 4 + 3] = h4.w + acc[n * 4 + 3] + bb[3];
        }
    }
    float4 gv = *(const float4*)&lng[cg * 4];
    float4 bv = *(const float4*)&lnb[cg * 4];
    float hn[16];
#pragma unroll
    for (int n = 0; n < 4; n++) {
        float s1 = pre[n*4] + pre[n*4+1] + pre[n*4+2] + pre[n*4+3];
        float s2 = pre[n*4]*pre[n*4] + pre[n*4+1]*pre[n*4+1]
                 + pre[n*4+2]*pre[n*4+2] + pre[n*4+3]*pre[n*4+3];
#pragma unroll
        for (int m = 1; m < 16; m <<= 1) {
            s1 += __shfl_xor_sync(0xffffffffu, s1, m);
            s2 += __shfl_xor_sync(0xffffffffu, s2, m);
        }
        float mean = s1 * (1.f / HH);
        float var  = s2 * (1.f / HH) - mean * mean;
        float inv  = rsqrtf(var + 1e-5f);
        hn[n*4+0] = (pre[n*4+0] - mean) * inv * gv.x + bv.x;
        hn[n*4+1] = (pre[n*4+1] - mean) * inv * gv.y + bv.y;
        hn[n*4+2] = (pre[n*4+2] - mean) * inv * gv.z + bv.z;
        hn[n*4+3] = (pre[n*4+3] - mean) * inv * gv.w + bv.w;
    }

    if (mode == 1) {
#pragma unroll
        for (int n = 0; n < 4; n++) {
            int node = n0 + ng * 4 + n;
            if (node < NN)
                *(float4*)&g_ah[(size_t)node * 128 + 64 + cg * 4] =
                    make_float4(hn[n*4], hn[n*4+1], hn[n*4+2], hn[n*4+3]);
        }
        __syncthreads();
#pragma unroll
        for (int n = 0; n < 4; n++)
#pragma unroll
            for (int c = 0; c < 4; c++)
                sA[cg * 4 + c][ng * 4 + n] = hn[n * 4 + c];
        STAGE_WD(sWd, gw1);
        __syncthreads();

        zero8(acc2);
        MATVEC_X2(sA, sWd, acc2);
        UNPACK_ACC(acc2, acc);
#pragma unroll
        for (int n = 0; n < 4; n++) {
            int node = n0 + ng * 4 + n;
            if (node < NN)
                *(float4*)&g_ah[(size_t)node * 128 + cg * 4] =
                    make_float4(acc[n*4], acc[n*4+1], acc[n*4+2], acc[n*4+3]);
        }
        __syncthreads();
        STAGE_WD(sWd, gw1 + (size_t)64 * HH);
        __syncthreads();

        zero8(acc2);
        MATVEC_X2(sA, sWd, acc2);
        UNPACK_ACC(acc2, acc);
        float4 gbv = *(const float4*)&gb1[cg * 4];
        float gb[4] = {gbv.x, gbv.y, gbv.z, gbv.w};
#pragma unroll
        for (int n = 0; n < 4; n++) {
            int node = n0 + ng * 4 + n;
            if (node < NN)
                *(float4*)&g_b[(size_t)node * HH + cg * 4] =
                    make_float4(acc[n*4] + gb[0], acc[n*4+1] + gb[1],
                                acc[n*4+2] + gb[2], acc[n*4+3] + gb[3]);
        }
    } else {
        // fused head: U = softplus(h @ toU_w + toU_b)
        __syncthreads();
#pragma unroll
        for (int n = 0; n < 4; n++)
#pragma unroll
            for (int c = 0; c < 4; c++)
                sA[cg * 4 + c][ng * 4 + n] = hn[n * 4 + c];
        // stage toU_w (64 x 32) plain into sWd rows
#pragma unroll
        for (int q = 0; q < 2; q++) {
            int lin = q * 256 + tid;
            int row = lin >> 3, c4 = (lin & 7) * 4;
            *(float4*)&sWd[row][c4] = *(const float4*)&tw[row * KK + c4];
        }
        __syncthreads();

        int cg2 = tid & 7, ng2 = tid >> 3;   // 8 col-groups x 32 node-groups
        float a8[8];
#pragma unroll
        for (int k = 0; k < 8; k++) a8[k] = 0.f;
#pragma unroll 8
        for (int i = 0; i < 64; i++) {
            float2 a2 = *(float2*)&sA[i][ng2 * 2];
            float4 w4 = *(float4*)&sWd[i][cg2 * 4];
            a8[0] = fmaf(a2.x, w4.x, a8[0]); a8[1] = fmaf(a2.x, w4.y, a8[1]);
            a8[2] = fmaf(a2.x, w4.z, a8[2]); a8[3] = fmaf(a2.x, w4.w, a8[3]);
            a8[4] = fmaf(a2.y, w4.x, a8[4]); a8[5] = fmaf(a2.y, w4.y, a8[5]);
            a8[6] = fmaf(a2.y, w4.z, a8[6]); a8[7] = fmaf(a2.y, w4.w, a8[7]);
        }
        float4 tb4 = *(const float4*)&tb[cg2 * 4];
        float tbb[4] = {tb4.x, tb4.y, tb4.z, tb4.w};
#pragma unroll
        for (int n = 0; n < 2; n++) {
            int node = n0 + ng2 * 2 + n;
            if (node < NN) {
                float4 o;
                float v0 = a8[n*4+0] + tbb[0];
                float v1 = a8[n*4+1] + tbb[1];
                float v2 = a8[n*4+2] + tbb[2];
                float v3 = a8[n*4+3] + tbb[3];
                o.x = log1pf(__expf(-fabsf(v0))) + fmaxf(v0, 0.f);
                o.y = log1pf(__expf(-fabsf(v1))) + fmaxf(v1, 0.f);
                o.z = log1pf(__expf(-fabsf(v2))) + fmaxf(v2, 0.f);
                o.w = log1pf(__expf(-fabsf(v3))) + fmaxf(v3, 0.f);
                *(float4*)&out[(size_t)node * KK + cg2 * 4] = o;
            }
        }
    }
}

// =====================================================================
extern "C" void kernel_launch(void* const* d_in, const int* in_sizes, int n_in,
                              void* d_out, int out_size) {
    const float* x      = (const float*)d_in[0];
    const int*   src    = (const int*)  d_in[1];
    const int*   dst    = (const int*)  d_in[2];
    const float* basew  = (const float*)d_in[3];
    const float* enc_w1 = (const float*)d_in[4];
    const float* enc_b1 = (const float*)d_in[5];
    const float* enc_w2 = (const float*)d_in[6];
    const float* enc_b2 = (const float*)d_in[7];
    const float* gw1    = (const float*)d_in[8];
    const float* gb1    = (const float*)d_in[9];
    const float* gw2    = (const float*)d_in[10];
    const float* gb2    = (const float*)d_in[11];
    const float* uw1    = (const float*)d_in[12];
    const float* ub1    = (const float*)d_in[13];
    const float* uw2    = (const float*)d_in[14];
    const float* ub2    = (const float*)d_in[15];
    const float* lng    = (const float*)d_in[16];
    const float* lnb    = (const float*)d_in[17];
    const float* rho    = (const float*)d_in[18];
    const float* tw     = (const float*)d_in[19];
    const float* tb     = (const float*)d_in[20];
    float* out = (float*)d_out;

    cudaFuncSetAttribute(k_encoder, cudaFuncAttributeMaxDynamicSharedMemorySize, DSM_BYTES);
    cudaFuncSetAttribute(k_update,  cudaFuncAttributeMaxDynamicSharedMemorySize, DSM_BYTES);

    int nblocks = (NN + NB - 1) / NB;
    k_encoder<<<nblocks, 256, DSM_BYTES>>>(x, enc_w1, enc_b1, enc_w2, enc_b2, gw1, gb1);
    k_rho<<<(NN + 255) / 256, 256>>>(rho);
    k_w0<<<(EE + 255) / 256, 256>>>(src, dst, basew);

    for (int l = 0; l < LL; l++) {
        k_edge<<<EE / 32, 256>>>(gw2, gb2);
        k_update<<<nblocks, 256, DSM_BYTES>>>(uw1 + l * HH * HH, ub1 + l * HH,
                                              uw2 + l * HH * HH, ub2 + l * HH,
                                              lng + l * HH, lnb + l * HH,
                                              gw1, gb1, tw, tb, out,
                                              l < LL - 1 ? 1 : 0);
    }
}

// round 11
// speedup vs baseline: 1.6893x; 1.6893x over previous
#include <cuda_runtime.h>
#include <math.h>

#define NN 50000
#define CC 256
#define EE 800000
#define HH 64
#define KK 32
#define LL 2
#define NB 64   // nodes per block in tiled node kernels

// ---- scratch (no allocation allowed) ----
__device__ float g_ah[NN * 128];   // per node: [0:64) gate-a proj, [64:128) h
__device__ float g_m[NN * HH];     // scatter accumulator (zero-invariant between replays)
__device__ float g_deg[NN];        // weighted degree (zero-invariant between replays)
__device__ float g_b[NN * HH];     // per-node dst-side gate projection: h @ W1[64:128] + b1
__device__ float g_w0[EE];         // base_w * rho[src] * rho[dst]  (layer-invariant)
__device__ int   g_soff[EE];       // src * 128  (element offset into g_ah)
__device__ int   g_doff[EE];       // dst * 64   (element offset into g_b / g_m)

// 4x4 outer-product FMA tile: acc[n*4+c] += av.n * wv.c
__device__ __forceinline__ void mm16(const float4 av, const float4 wv, float* acc) {
    acc[0]  = fmaf(av.x, wv.x, acc[0]);  acc[1]  = fmaf(av.x, wv.y, acc[1]);
    acc[2]  = fmaf(av.x, wv.z, acc[2]);  acc[3]  = fmaf(av.x, wv.w, acc[3]);
    acc[4]  = fmaf(av.y, wv.x, acc[4]);  acc[5]  = fmaf(av.y, wv.y, acc[5]);
    acc[6]  = fmaf(av.y, wv.z, acc[6]);  acc[7]  = fmaf(av.y, wv.w, acc[7]);
    acc[8]  = fmaf(av.z, wv.x, acc[8]);  acc[9]  = fmaf(av.z, wv.y, acc[9]);
    acc[10] = fmaf(av.z, wv.z, acc[10]); acc[11] = fmaf(av.z, wv.w, acc[11]);
    acc[12] = fmaf(av.w, wv.x, acc[12]); acc[13] = fmaf(av.w, wv.y, acc[13]);
    acc[14] = fmaf(av.w, wv.z, acc[14]); acc[15] = fmaf(av.w, wv.w, acc[15]);
}

__device__ __forceinline__ void zero16(float* acc) {
#pragma unroll
    for (int k = 0; k < 16; k++) acc[k] = 0.f;
}

__device__ __forceinline__ void red_v4(float* addr, float4 v) {
    asm volatile("red.global.add.v4.f32 [%0], {%1, %2, %3, %4};"
                 :: "l"(addr), "f"(v.x), "f"(v.y), "f"(v.z), "f"(v.w) : "memory");
}

// stage a 64x64 row-major global matrix into sW[64][68]
#define STAGE_W(sW, gptr) do {                                            \
    _Pragma("unroll")                                                     \
    for (int _q = 0; _q < 4; _q++) {                                      \
        int _lin = _q * 256 + tid;                                        \
        *(float4*)&sW[_lin >> 4][(_lin & 15) * 4] =                       \
            *(const float4*)&(gptr)[_lin * 4];                            \
    }                                                                     \
} while (0)

// tiled matvec: acc[16] += sA(64 x nodes) x sW(64 x ch) tile at (ng, cg)
#define MATVEC(sA, sW, acc) do {                                          \
    _Pragma("unroll 8")                                                   \
    for (int _i = 0; _i < 64; _i++) {                                     \
        float4 _av = *(float4*)&sA[_i][ng * 4];                           \
        float4 _wv = *(float4*)&sW[_i][cg * 4];                           \
        mm16(_av, _wv, acc);                                              \
    }                                                                     \
} while (0)

// =====================================================================
// Encoder (tiled): h = relu(relu(x @ W1 + b1) @ W2 + b2), then fused
// gate pre-projections a = h@gW1[0:64] -> g_ah[:,0:64],
// h -> g_ah[:,64:128], b = h@gW1[64:128]+gb1 -> g_b.
// =====================================================================
__global__ void __launch_bounds__(256) k_encoder(
        const float* __restrict__ x,
        const float* __restrict__ w1, const float* __restrict__ b1,
        const float* __restrict__ w2, const float* __restrict__ b2,
        const float* __restrict__ gw1, const float* __restrict__ gb1) {
    __shared__ float sA[64][NB + 4];
    __shared__ float sW[64][68];
    int tid = threadIdx.x;
    int cg = tid & 15, ng = tid >> 4;
    int n0 = blockIdx.x * NB;

    float acc[16];
    zero16(acc);

    // ---- layer1: K=256 in 4 chunks of 64 ----
    for (int kb = 0; kb < 4; kb++) {
#pragma unroll
        for (int q = 0; q < 4; q++) {
            int lin = q * 256 + tid;
            int node = lin >> 4;
            int c4 = (lin & 15) * 4;
            int n = n0 + node;
            float4 v = make_float4(0.f, 0.f, 0.f, 0.f);
            if (n < NN) v = *(const float4*)&x[(size_t)n * CC + kb * 64 + c4];
            sA[c4 + 0][node] = v.x; sA[c4 + 1][node] = v.y;
            sA[c4 + 2][node] = v.z; sA[c4 + 3][node] = v.w;
        }
        STAGE_W(sW, w1 + (size_t)kb * 64 * HH);
        __syncthreads();
        MATVEC(sA, sW, acc);
        __syncthreads();
    }

    // h1 = relu(acc + b1); write transposed into sA, stage w2
    {
        float4 bv = *(const float4*)&b1[cg * 4];
        float bb[4] = {bv.x, bv.y, bv.z, bv.w};
#pragma unroll
        for (int n = 0; n < 4; n++)
#pragma unroll
            for (int c = 0; c < 4; c++)
                sA[cg * 4 + c][ng * 4 + n] = fmaxf(acc[n * 4 + c] + bb[c], 0.f);
    }
    STAGE_W(sW, w2);
    __syncthreads();

    zero16(acc);
    MATVEC(sA, sW, acc);
    __syncthreads();

    // h = relu(acc + b2); store to g_ah[:,64:], write transposed into sA
    float hval[16];
    {
        float4 bv = *(const float4*)&b2[cg * 4];
        float bb[4] = {bv.x, bv.y, bv.z, bv.w};
#pragma unroll
        for (int n = 0; n < 4; n++) {
            int node = n0 + ng * 4 + n;
#pragma unroll
            for (int c = 0; c < 4; c++) {
                hval[n * 4 + c] = fmaxf(acc[n * 4 + c] + bb[c], 0.f);
                sA[cg * 4 + c][ng * 4 + n] = hval[n * 4 + c];
            }
            if (node < NN)
                *(float4*)&g_ah[(size_t)node * 128 + 64 + cg * 4] =
                    make_float4(hval[n*4], hval[n*4+1], hval[n*4+2], hval[n*4+3]);
        }
    }
    STAGE_W(sW, gw1);                 // first 64 rows of gate W1
    __syncthreads();

    zero16(acc);
    MATVEC(sA, sW, acc);
#pragma unroll
    for (int n = 0; n < 4; n++) {
        int node = n0 + ng * 4 + n;
        if (node < NN)
            *(float4*)&g_ah[(size_t)node * 128 + cg * 4] =
                make_float4(acc[n*4], acc[n*4+1], acc[n*4+2], acc[n*4+3]);
    }
    __syncthreads();
    STAGE_W(sW, gw1 + (size_t)64 * HH);  // second 64 rows
    __syncthreads();

    zero16(acc);
    MATVEC(sA, sW, acc);
    {
        float4 bv = *(const float4*)&gb1[cg * 4];
        float bb[4] = {bv.x, bv.y, bv.z, bv.w};
#pragma unroll
        for (int n = 0; n < 4; n++) {
            int node = n0 + ng * 4 + n;
            if (node < NN)
                *(float4*)&g_b[(size_t)node * HH + cg * 4] =
                    make_float4(acc[n*4] + bb[0], acc[n*4+1] + bb[1],
                                acc[n*4+2] + bb[2], acc[n*4+3] + bb[3]);
        }
    }
}

// =====================================================================
// w0[e] = base_w * sigmoid(rho_raw[src]) * sigmoid(rho_raw[dst]);
// plus precomputed gather offsets. (k_rho folded in.)
// =====================================================================
__global__ void k_w0(const int* __restrict__ src, const int* __restrict__ dst,
                     const float* __restrict__ basew,
                     const float* __restrict__ rho_raw) {
    int i = blockIdx.x * blockDim.x + threadIdx.x;
    if (i < EE) {
        int s = src[i], d = dst[i];
        float rs = 1.f / (1.f + __expf(-rho_raw[s]));
        float rd = 1.f / (1.f + __expf(-rho_raw[d]));
        g_w0[i] = basew[i] * rs * rd;
        g_soff[i] = s * 128;
        g_doff[i] = d * 64;
    }
}

// =====================================================================
// Edge kernel: half-warp per edge; lane owns 4 channels.
// Uses precomputed offsets (no per-edge index multiplies).
//   z = relu(a[src] + b[dst]); gate = sigmoid(z @ w2 + b2)
//   wt = w0[e] * gate;  red.v4: m[dst] += wt*h_src ; deg[dst] += wt
// grid = EE/32 exactly.
// =====================================================================
__global__ void __launch_bounds__(256) k_edge(
        const float* __restrict__ gw2, const float* __restrict__ gb2) {
    __shared__ float4 sw2[16];
    __shared__ float sb2;
    int tid = threadIdx.x;
    if (tid < 16) sw2[tid] = *(const float4*)&gw2[tid * 4];
    if (tid == 0) sb2 = gb2[0];
    __syncthreads();

    int lane = tid & 31;
    int warp = tid >> 5;
    int sub = lane >> 4;       // which half-warp
    int sl  = lane & 15;       // lane within half
    int e0 = (blockIdx.x * 8 + warp) * 4;

    int4 so4 = *(const int4*)&g_soff[e0];
    int4 do4 = *(const int4*)&g_doff[e0];
    float4 w04 = *(const float4*)&g_w0[e0];
    int soE[4] = {so4.x, so4.y, so4.z, so4.w};
    int doE[4] = {do4.x, do4.y, do4.z, do4.w};
    float w0E[4] = {w04.x, w04.y, w04.z, w04.w};

    float4 w2v = sw2[sl];
    float b2v = sb2;

    int doI[2];
    float4 av[2], bv[2], hv[2];
    float w0I[2];
#pragma unroll
    for (int t = 0; t < 2; t++) {
        int ei = t * 2 + sub;
        doI[t] = doE[ei]; w0I[t] = w0E[ei];
        const float* ahp = g_ah + soE[ei] + sl * 4;
        av[t] = *(const float4*)ahp;
        hv[t] = *(const float4*)(ahp + 64);
        bv[t] = *(const float4*)(g_b + doI[t] + sl * 4);
    }

    float part[2];
#pragma unroll
    for (int t = 0; t < 2; t++)
        part[t] = fmaxf(av[t].x + bv[t].x, 0.f) * w2v.x
                + fmaxf(av[t].y + bv[t].y, 0.f) * w2v.y
                + fmaxf(av[t].z + bv[t].z, 0.f) * w2v.z
                + fmaxf(av[t].w + bv[t].w, 0.f) * w2v.w;

#pragma unroll
    for (int off = 8; off; off >>= 1) {
        part[0] += __shfl_xor_sync(0xffffffffu, part[0], off);
        part[1] += __shfl_xor_sync(0xffffffffu, part[1], off);
    }

#pragma unroll
    for (int t = 0; t < 2; t++) {
        float gate = 1.f / (1.f + __expf(-(part[t] + b2v)));
        float wt = w0I[t] * gate;
        float4 mv = make_float4(wt * hv[t].x, wt * hv[t].y,
                                wt * hv[t].z, wt * hv[t].w);
        red_v4(&g_m[doI[t] + sl * 4], mv);
        if (sl == 0) atomicAdd(&g_deg[doI[t] >> 6], wt);
    }
}

// =====================================================================
// Node update (tiled) + LayerNorm + either next-layer gate projections
// (mode=1) or fused output head (mode=0).
// block = 256 threads, 64 nodes/block. Resets g_m/g_deg (replay invariant).
// =====================================================================
__global__ void __launch_bounds__(256) k_update(
        const float* __restrict__ uw1, const float* __restrict__ ub1,
        const float* __restrict__ uw2, const float* __restrict__ ub2,
        const float* __restrict__ lng, const float* __restrict__ lnb,
        const float* __restrict__ gw1, const float* __restrict__ gb1,
        const float* __restrict__ tw, const float* __restrict__ tb,
        float* __restrict__ out, int mode) {
    __shared__ float sA[64][NB + 4];
    __shared__ float sW[64][68];
    __shared__ float sInv[NB];
    int tid = threadIdx.x;
    int cg = tid & 15, ng = tid >> 4;
    int n0 = blockIdx.x * NB;

    if (tid < NB) {
        int n = n0 + tid;
        float deg = (n < NN) ? g_deg[n] : 0.f;
        sInv[tid] = 1.f / (deg + 1e-8f);
        if (n < NN) g_deg[n] = 0.f;
    }
    __syncthreads();

    // stage neigh = m*inv transposed; reset g_m; stage uw1
#pragma unroll
    for (int q = 0; q < 4; q++) {
        int lin = q * 256 + tid;
        int node = lin >> 4;
        int c4 = (lin & 15) * 4;
        int n = n0 + node;
        float4 v = make_float4(0.f, 0.f, 0.f, 0.f);
        if (n < NN) {
            v = *(const float4*)&g_m[(size_t)n * HH + c4];
            *(float4*)&g_m[(size_t)n * HH + c4] = make_float4(0.f, 0.f, 0.f, 0.f);
        }
        float inv = sInv[node];
        sA[c4 + 0][node] = v.x * inv; sA[c4 + 1][node] = v.y * inv;
        sA[c4 + 2][node] = v.z * inv; sA[c4 + 3][node] = v.w * inv;
    }
    STAGE_W(sW, uw1);
    __syncthreads();

    float acc[16];
    zero16(acc);
    MATVEC(sA, sW, acc);
    __syncthreads();

    // t = relu(acc + ub1) -> transposed into sA; stage uw2
    {
        float4 bv = *(const float4*)&ub1[cg * 4];
        float bb[4] = {bv.x, bv.y, bv.z, bv.w};
#pragma unroll
        for (int n = 0; n < 4; n++)
#pragma unroll
            for (int c = 0; c < 4; c++)
                sA[cg * 4 + c][ng * 4 + n] = fmaxf(acc[n * 4 + c] + bb[c], 0.f);
    }
    STAGE_W(sW, uw2);
    __syncthreads();

    zero16(acc);
    MATVEC(sA, sW, acc);

    // pre = h + u; LayerNorm per node (reduce over 16 cg-threads)
    float pre[16];
    {
        float4 bv = *(const float4*)&ub2[cg * 4];
        float bb[4] = {bv.x, bv.y, bv.z, bv.w};
#pragma unroll
        for (int n = 0; n < 4; n++) {
            int node = n0 + ng * 4 + n;
            float4 h4 = make_float4(0.f, 0.f, 0.f, 0.f);
            if (node < NN)
                h4 = *(const float4*)&g_ah[(size_t)node * 128 + 64 + cg * 4];
            pre[n * 4 + 0] = h4.x + acc[n * 4 + 0] + bb[0];
            pre[n * 4 + 1] = h4.y + acc[n * 4 + 1] + bb[1];
            pre[n * 4 + 2] = h4.z + acc[n * 4 + 2] + bb[2];
            pre[n * 4 + 3] = h4.w + acc[n * 4 + 3] + bb[3];
        }
    }
    float4 gv = *(const float4*)&lng[cg * 4];
    float4 bv = *(const float4*)&lnb[cg * 4];
    float hn[16];
#pragma unroll
    for (int n = 0; n < 4; n++) {
        float s1 = pre[n*4] + pre[n*4+1] + pre[n*4+2] + pre[n*4+3];
        float s2 = pre[n*4]*pre[n*4] + pre[n*4+1]*pre[n*4+1]
                 + pre[n*4+2]*pre[n*4+2] + pre[n*4+3]*pre[n*4+3];
#pragma unroll
        for (int m = 1; m < 16; m <<= 1) {
            s1 += __shfl_xor_sync(0xffffffffu, s1, m);
            s2 += __shfl_xor_sync(0xffffffffu, s2, m);
        }
        float mean = s1 * (1.f / HH);
        float var  = s2 * (1.f / HH) - mean * mean;
        float inv  = rsqrtf(var + 1e-5f);
        hn[n*4+0] = (pre[n*4+0] - mean) * inv * gv.x + bv.x;
        hn[n*4+1] = (pre[n*4+1] - mean) * inv * gv.y + bv.y;
        hn[n*4+2] = (pre[n*4+2] - mean) * inv * gv.z + bv.z;
        hn[n*4+3] = (pre[n*4+3] - mean) * inv * gv.w + bv.w;
    }

    if (mode == 1) {
        // write new h; compute next-layer gate projections a/b
#pragma unroll
        for (int n = 0; n < 4; n++) {
            int node = n0 + ng * 4 + n;
            if (node < NN)
                *(float4*)&g_ah[(size_t)node * 128 + 64 + cg * 4] =
                    make_float4(hn[n*4], hn[n*4+1], hn[n*4+2], hn[n*4+3]);
        }
        __syncthreads();   // all reads of sA/sW done
#pragma unroll
        for (int n = 0; n < 4; n++)
#pragma unroll
            for (int c = 0; c < 4; c++)
                sA[cg * 4 + c][ng * 4 + n] = hn[n * 4 + c];
        STAGE_W(sW, gw1);
        __syncthreads();

        zero16(acc);
        MATVEC(sA, sW, acc);
#pragma unroll
        for (int n = 0; n < 4; n++) {
            int node = n0 + ng * 4 + n;
            if (node < NN)
                *(float4*)&g_ah[(size_t)node * 128 + cg * 4] =
                    make_float4(acc[n*4], acc[n*4+1], acc[n*4+2], acc[n*4+3]);
        }
        __syncthreads();
        STAGE_W(sW, gw1 + (size_t)64 * HH);
        __syncthreads();

        zero16(acc);
        MATVEC(sA, sW, acc);
        float4 gbv = *(const float4*)&gb1[cg * 4];
        float gb[4] = {gbv.x, gbv.y, gbv.z, gbv.w};
#pragma unroll
        for (int n = 0; n < 4; n++) {
            int node = n0 + ng * 4 + n;
            if (node < NN)
                *(float4*)&g_b[(size_t)node * HH + cg * 4] =
                    make_float4(acc[n*4] + gb[0], acc[n*4+1] + gb[1],
                                acc[n*4+2] + gb[2], acc[n*4+3] + gb[3]);
        }
    } else {
        // fused head: U = softplus(h @ toU_w + toU_b)
        __syncthreads();   // all reads of sA/sW done
#pragma unroll
        for (int n = 0; n < 4; n++)
#pragma unroll
            for (int c = 0; c < 4; c++)
                sA[cg * 4 + c][ng * 4 + n] = hn[n * 4 + c];
        // stage toU_w (64 x 32) into sW[:, 0:32]
#pragma unroll
        for (int q = 0; q < 2; q++) {
            int lin = q * 256 + tid;
            int row = lin >> 3, c4 = (lin & 7) * 4;
            *(float4*)&sW[row][c4] = *(const float4*)&tw[row * KK + c4];
        }
        __syncthreads();

        int cg2 = tid & 7, ng2 = tid >> 3;   // 8 col-groups x 32 node-groups
        float a8[8];
#pragma unroll
        for (int k = 0; k < 8; k++) a8[k] = 0.f;
#pragma unroll 8
        for (int i = 0; i < 64; i++) {
            float2 a2 = *(float2*)&sA[i][ng2 * 2];
            float4 w4 = *(float4*)&sW[i][cg2 * 4];
            a8[0] = fmaf(a2.x, w4.x, a8[0]); a8[1] = fmaf(a2.x, w4.y, a8[1]);
            a8[2] = fmaf(a2.x, w4.z, a8[2]); a8[3] = fmaf(a2.x, w4.w, a8[3]);
            a8[4] = fmaf(a2.y, w4.x, a8[4]); a8[5] = fmaf(a2.y, w4.y, a8[5]);
            a8[6] = fmaf(a2.y, w4.z, a8[6]); a8[7] = fmaf(a2.y, w4.w, a8[7]);
        }
        float4 tb4 = *(const float4*)&tb[cg2 * 4];
        float tbb[4] = {tb4.x, tb4.y, tb4.z, tb4.w};
#pragma unroll
        for (int n = 0; n < 2; n++) {
            int node = n0 + ng2 * 2 + n;
            if (node < NN) {
                float4 o;
                float v0 = a8[n*4+0] + tbb[0];
                float v1 = a8[n*4+1] + tbb[1];
                float v2 = a8[n*4+2] + tbb[2];
                float v3 = a8[n*4+3] + tbb[3];
                o.x = log1pf(__expf(-fabsf(v0))) + fmaxf(v0, 0.f);
                o.y = log1pf(__expf(-fabsf(v1))) + fmaxf(v1, 0.f);
                o.z = log1pf(__expf(-fabsf(v2))) + fmaxf(v2, 0.f);
                o.w = log1pf(__expf(-fabsf(v3))) + fmaxf(v3, 0.f);
                *(float4*)&out[(size_t)node * KK + cg2 * 4] = o;
            }
        }
    }
}

// =====================================================================
extern "C" void kernel_launch(void* const* d_in, const int* in_sizes, int n_in,
                              void* d_out, int out_size) {
    const float* x      = (const float*)d_in[0];
    const int*   src    = (const int*)  d_in[1];
    const int*   dst    = (const int*)  d_in[2];
    const float* basew  = (const float*)d_in[3];
    const float* enc_w1 = (const float*)d_in[4];
    const float* enc_b1 = (const float*)d_in[5];
    const float* enc_w2 = (const float*)d_in[6];
    const float* enc_b2 = (const float*)d_in[7];
    const float* gw1    = (const float*)d_in[8];
    const float* gb1    = (const float*)d_in[9];
    const float* gw2    = (const float*)d_in[10];
    const float* gb2    = (const float*)d_in[11];
    const float* uw1    = (const float*)d_in[12];
    const float* ub1    = (const float*)d_in[13];
    const float* uw2    = (const float*)d_in[14];
    const float* ub2    = (const float*)d_in[15];
    const float* lng    = (const float*)d_in[16];
    const float* lnb    = (const float*)d_in[17];
    const float* rho    = (const float*)d_in[18];
    const float* tw     = (const float*)d_in[19];
    const float* tb     = (const float*)d_in[20];
    float* out = (float*)d_out;

    int nblocks = (NN + NB - 1) / NB;
    k_encoder<<<nblocks, 256>>>(x, enc_w1, enc_b1, enc_w2, enc_b2, gw1, gb1);
    k_w0<<<(EE + 255) / 256, 256>>>(src, dst, basew, rho);

    for (int l = 0; l < LL; l++) {
        k_edge<<<EE / 32, 256>>>(gw2, gb2);
        k_update<<<nblocks, 256>>>(uw1 + l * HH * HH, ub1 + l * HH,
                                   uw2 + l * HH * HH, ub2 + l * HH,
                                   lng + l * HH, lnb + l * HH,
                                   gw1, gb1, tw, tb, out,
                                   l < LL - 1 ? 1 : 0);
    }
}

// round 12
// speedup vs baseline: 1.7086x; 1.0114x over previous
#include <cuda_runtime.h>
#include <math.h>

#define NN 50000
#define CC 256
#define EE 800000
#define HH 64
#define KK 32
#define LL 2
#define NB 64   // nodes per block in tiled node kernels

// ---- scratch (no allocation allowed) ----
__device__ float g_ah[NN * 128];   // per node: [0:64) gate-a proj, [64:128) h
__device__ float g_m[NN * HH];     // scatter accumulator (zero-invariant between replays)
__device__ float g_deg[NN];        // weighted degree (zero-invariant between replays)
__device__ float g_b[NN * HH];     // per-node dst-side gate projection: h @ W1[64:128] + b1
__device__ float g_w0[EE];         // base_w * rho[src] * rho[dst]  (layer-invariant)
__device__ int   g_soff[EE];       // src * 128  (element offset into g_ah)
__device__ int   g_doff[EE];       // dst * 64   (element offset into g_b / g_m)

// 4x4 outer-product FMA tile: acc[n*4+c] += av.n * wv.c
__device__ __forceinline__ void mm16(const float4 av, const float4 wv, float* acc) {
    acc[0]  = fmaf(av.x, wv.x, acc[0]);  acc[1]  = fmaf(av.x, wv.y, acc[1]);
    acc[2]  = fmaf(av.x, wv.z, acc[2]);  acc[3]  = fmaf(av.x, wv.w, acc[3]);
    acc[4]  = fmaf(av.y, wv.x, acc[4]);  acc[5]  = fmaf(av.y, wv.y, acc[5]);
    acc[6]  = fmaf(av.y, wv.z, acc[6]);  acc[7]  = fmaf(av.y, wv.w, acc[7]);
    acc[8]  = fmaf(av.z, wv.x, acc[8]);  acc[9]  = fmaf(av.z, wv.y, acc[9]);
    acc[10] = fmaf(av.z, wv.z, acc[10]); acc[11] = fmaf(av.z, wv.w, acc[11]);
    acc[12] = fmaf(av.w, wv.x, acc[12]); acc[13] = fmaf(av.w, wv.y, acc[13]);
    acc[14] = fmaf(av.w, wv.z, acc[14]); acc[15] = fmaf(av.w, wv.w, acc[15]);
}

__device__ __forceinline__ void zero16(float* acc) {
#pragma unroll
    for (int k = 0; k < 16; k++) acc[k] = 0.f;
}

__device__ __forceinline__ void red_v4(float* addr, float4 v) {
    asm volatile("red.global.add.v4.f32 [%0], {%1, %2, %3, %4};"
                 :: "l"(addr), "f"(v.x), "f"(v.y), "f"(v.z), "f"(v.w) : "memory");
}

// stage a 64x64 row-major global matrix into sW[64][68]
#define STAGE_W(sW, gptr) do {                                            \
    _Pragma("unroll")                                                     \
    for (int _q = 0; _q < 4; _q++) {                                      \
        int _lin = _q * 256 + tid;                                        \
        *(float4*)&sW[_lin >> 4][(_lin & 15) * 4] =                       \
            *(const float4*)&(gptr)[_lin * 4];                            \
    }                                                                     \
} while (0)

// tiled matvec: acc[16] += sA(64 x nodes) x sW(64 x ch) tile at (ng, cg)
#define MATVEC(sA, sW, acc) do {                                          \
    _Pragma("unroll 8")                                                   \
    for (int _i = 0; _i < 64; _i++) {                                     \
        float4 _av = *(float4*)&sA[_i][ng * 4];                           \
        float4 _wv = *(float4*)&sW[_i][cg * 4];                           \
        mm16(_av, _wv, acc);                                              \
    }                                                                     \
} while (0)

// =====================================================================
// Encoder (tiled): h = relu(relu(x @ W1 + b1) @ W2 + b2), then fused
// gate pre-projections a = h@gW1[0:64] -> g_ah[:,0:64],
// h -> g_ah[:,64:128], b = h@gW1[64:128]+gb1 -> g_b.
// =====================================================================
__global__ void __launch_bounds__(256) k_encoder(
        const float* __restrict__ x,
        const float* __restrict__ w1, const float* __restrict__ b1,
        const float* __restrict__ w2, const float* __restrict__ b2,
        const float* __restrict__ gw1, const float* __restrict__ gb1) {
    __shared__ float sA[64][NB + 4];
    __shared__ float sW[64][68];
    int tid = threadIdx.x;
    int cg = tid & 15, ng = tid >> 4;
    int n0 = blockIdx.x * NB;

    float acc[16];
    zero16(acc);

    // ---- layer1: K=256 in 4 chunks of 64 ----
    for (int kb = 0; kb < 4; kb++) {
#pragma unroll
        for (int q = 0; q < 4; q++) {
            int lin = q * 256 + tid;
            int node = lin >> 4;
            int c4 = (lin & 15) * 4;
            int n = n0 + node;
            float4 v = make_float4(0.f, 0.f, 0.f, 0.f);
            if (n < NN) v = *(const float4*)&x[(size_t)n * CC + kb * 64 + c4];
            sA[c4 + 0][node] = v.x; sA[c4 + 1][node] = v.y;
            sA[c4 + 2][node] = v.z; sA[c4 + 3][node] = v.w;
        }
        STAGE_W(sW, w1 + (size_t)kb * 64 * HH);
        __syncthreads();
        MATVEC(sA, sW, acc);
        __syncthreads();
    }

    // h1 = relu(acc + b1); write transposed into sA, stage w2
    {
        float4 bv = *(const float4*)&b1[cg * 4];
        float bb[4] = {bv.x, bv.y, bv.z, bv.w};
#pragma unroll
        for (int n = 0; n < 4; n++)
#pragma unroll
            for (int c = 0; c < 4; c++)
                sA[cg * 4 + c][ng * 4 + n] = fmaxf(acc[n * 4 + c] + bb[c], 0.f);
    }
    STAGE_W(sW, w2);
    __syncthreads();

    zero16(acc);
    MATVEC(sA, sW, acc);
    __syncthreads();

    // h = relu(acc + b2); store to g_ah[:,64:], write transposed into sA
    float hval[16];
    {
        float4 bv = *(const float4*)&b2[cg * 4];
        float bb[4] = {bv.x, bv.y, bv.z, bv.w};
#pragma unroll
        for (int n = 0; n < 4; n++) {
            int node = n0 + ng * 4 + n;
#pragma unroll
            for (int c = 0; c < 4; c++) {
                hval[n * 4 + c] = fmaxf(acc[n * 4 + c] + bb[c], 0.f);
                sA[cg * 4 + c][ng * 4 + n] = hval[n * 4 + c];
            }
            if (node < NN)
                *(float4*)&g_ah[(size_t)node * 128 + 64 + cg * 4] =
                    make_float4(hval[n*4], hval[n*4+1], hval[n*4+2], hval[n*4+3]);
        }
    }
    STAGE_W(sW, gw1);                 // first 64 rows of gate W1
    __syncthreads();

    zero16(acc);
    MATVEC(sA, sW, acc);
#pragma unroll
    for (int n = 0; n < 4; n++) {
        int node = n0 + ng * 4 + n;
        if (node < NN)
            *(float4*)&g_ah[(size_t)node * 128 + cg * 4] =
                make_float4(acc[n*4], acc[n*4+1], acc[n*4+2], acc[n*4+3]);
    }
    __syncthreads();
    STAGE_W(sW, gw1 + (size_t)64 * HH);  // second 64 rows
    __syncthreads();

    zero16(acc);
    MATVEC(sA, sW, acc);
    {
        float4 bv = *(const float4*)&gb1[cg * 4];
        float bb[4] = {bv.x, bv.y, bv.z, bv.w};
#pragma unroll
        for (int n = 0; n < 4; n++) {
            int node = n0 + ng * 4 + n;
            if (node < NN)
                *(float4*)&g_b[(size_t)node * HH + cg * 4] =
                    make_float4(acc[n*4] + bb[0], acc[n*4+1] + bb[1],
                                acc[n*4+2] + bb[2], acc[n*4+3] + bb[3]);
        }
    }
}

// =====================================================================
// w0[e] = base_w * sigmoid(rho_raw[src]) * sigmoid(rho_raw[dst]);
// plus precomputed gather offsets.
// =====================================================================
__global__ void k_w0(const int* __restrict__ src, const int* __restrict__ dst,
                     const float* __restrict__ basew,
                     const float* __restrict__ rho_raw) {
    int i = blockIdx.x * blockDim.x + threadIdx.x;
    if (i < EE) {
        int s = src[i], d = dst[i];
        float rs = 1.f / (1.f + __expf(-rho_raw[s]));
        float rd = 1.f / (1.f + __expf(-rho_raw[d]));
        g_w0[i] = basew[i] * rs * rd;
        g_soff[i] = s * 128;
        g_doff[i] = d * 64;
    }
}

// =====================================================================
// Edge kernel: half-warp per edge; lane owns 4 channels.
// Barrier-free / smem-free: w2 and b2 loaded per-warp via __ldg (L1-hot).
//   z = relu(a[src] + b[dst]); gate = sigmoid(z @ w2 + b2)
//   wt = w0[e] * gate;  red.v4: m[dst] += wt*h_src ; deg[dst] += wt
// grid = EE/32 exactly.
// =====================================================================
__global__ void __launch_bounds__(256) k_edge(
        const float* __restrict__ gw2, const float* __restrict__ gb2) {
    int tid = threadIdx.x;
    int lane = tid & 31;
    int warp = tid >> 5;
    int sub = lane >> 4;       // which half-warp
    int sl  = lane & 15;       // lane within half
    int e0 = (blockIdx.x * 8 + warp) * 4;

    // per-warp weight loads (L1-resident after first blocks)
    float4 w2v = __ldg((const float4*)&gw2[sl * 4]);
    float b2v = __ldg(gb2);

    int4 so4 = *(const int4*)&g_soff[e0];
    int4 do4 = *(const int4*)&g_doff[e0];
    float4 w04 = *(const float4*)&g_w0[e0];
    int soE[4] = {so4.x, so4.y, so4.z, so4.w};
    int doE[4] = {do4.x, do4.y, do4.z, do4.w};
    float w0E[4] = {w04.x, w04.y, w04.z, w04.w};

    int doI[2];
    float4 av[2], bv[2], hv[2];
    float w0I[2];
#pragma unroll
    for (int t = 0; t < 2; t++) {
        int ei = t * 2 + sub;
        doI[t] = doE[ei]; w0I[t] = w0E[ei];
        const float* ahp = g_ah + soE[ei] + sl * 4;
        av[t] = *(const float4*)ahp;
        hv[t] = *(const float4*)(ahp + 64);
        bv[t] = *(const float4*)(g_b + doI[t] + sl * 4);
    }

    float part[2];
#pragma unroll
    for (int t = 0; t < 2; t++)
        part[t] = fmaxf(av[t].x + bv[t].x, 0.f) * w2v.x
                + fmaxf(av[t].y + bv[t].y, 0.f) * w2v.y
                + fmaxf(av[t].z + bv[t].z, 0.f) * w2v.z
                + fmaxf(av[t].w + bv[t].w, 0.f) * w2v.w;

#pragma unroll
    for (int off = 8; off; off >>= 1) {
        part[0] += __shfl_xor_sync(0xffffffffu, part[0], off);
        part[1] += __shfl_xor_sync(0xffffffffu, part[1], off);
    }

#pragma unroll
    for (int t = 0; t < 2; t++) {
        float gate = 1.f / (1.f + __expf(-(part[t] + b2v)));
        float wt = w0I[t] * gate;
        float4 mv = make_float4(wt * hv[t].x, wt * hv[t].y,
                                wt * hv[t].z, wt * hv[t].w);
        red_v4(&g_m[doI[t] + sl * 4], mv);
        if (sl == 0) atomicAdd(&g_deg[doI[t] >> 6], wt);
    }
}

// =====================================================================
// Node update (tiled) + LayerNorm + either next-layer gate projections
// (mode=1) or fused output head (mode=0).
// block = 256 threads, 64 nodes/block. Resets g_m/g_deg (replay invariant).
// =====================================================================
__global__ void __launch_bounds__(256) k_update(
        const float* __restrict__ uw1, const float* __restrict__ ub1,
        const float* __restrict__ uw2, const float* __restrict__ ub2,
        const float* __restrict__ lng, const float* __restrict__ lnb,
        const float* __restrict__ gw1, const float* __restrict__ gb1,
        const float* __restrict__ tw, const float* __restrict__ tb,
        float* __restrict__ out, int mode) {
    __shared__ float sA[64][NB + 4];
    __shared__ float sW[64][68];
    __shared__ float sInv[NB];
    int tid = threadIdx.x;
    int cg = tid & 15, ng = tid >> 4;
    int n0 = blockIdx.x * NB;

    if (tid < NB) {
        int n = n0 + tid;
        float deg = (n < NN) ? g_deg[n] : 0.f;
        sInv[tid] = 1.f / (deg + 1e-8f);
        if (n < NN) g_deg[n] = 0.f;
    }
    __syncthreads();

    // stage neigh = m*inv transposed; reset g_m; stage uw1
#pragma unroll
    for (int q = 0; q < 4; q++) {
        int lin = q * 256 + tid;
        int node = lin >> 4;
        int c4 = (lin & 15) * 4;
        int n = n0 + node;
        float4 v = make_float4(0.f, 0.f, 0.f, 0.f);
        if (n < NN) {
            v = *(const float4*)&g_m[(size_t)n * HH + c4];
            *(float4*)&g_m[(size_t)n * HH + c4] = make_float4(0.f, 0.f, 0.f, 0.f);
        }
        float inv = sInv[node];
        sA[c4 + 0][node] = v.x * inv; sA[c4 + 1][node] = v.y * inv;
        sA[c4 + 2][node] = v.z * inv; sA[c4 + 3][node] = v.w * inv;
    }
    STAGE_W(sW, uw1);
    __syncthreads();

    float acc[16];
    zero16(acc);
    MATVEC(sA, sW, acc);
    __syncthreads();

    // t = relu(acc + ub1) -> transposed into sA; stage uw2
    {
        float4 bv = *(const float4*)&ub1[cg * 4];
        float bb[4] = {bv.x, bv.y, bv.z, bv.w};
#pragma unroll
        for (int n = 0; n < 4; n++)
#pragma unroll
            for (int c = 0; c < 4; c++)
                sA[cg * 4 + c][ng * 4 + n] = fmaxf(acc[n * 4 + c] + bb[c], 0.f);
    }
    STAGE_W(sW, uw2);
    __syncthreads();

    zero16(acc);
    MATVEC(sA, sW, acc);

    // pre = h + u; LayerNorm per node (reduce over 16 cg-threads)
    float pre[16];
    {
        float4 bv = *(const float4*)&ub2[cg * 4];
        float bb[4] = {bv.x, bv.y, bv.z, bv.w};
#pragma unroll
        for (int n = 0; n < 4; n++) {
            int node = n0 + ng * 4 + n;
            float4 h4 = make_float4(0.f, 0.f, 0.f, 0.f);
            if (node < NN)
                h4 = *(const float4*)&g_ah[(size_t)node * 128 + 64 + cg * 4];
            pre[n * 4 + 0] = h4.x + acc[n * 4 + 0] + bb[0];
            pre[n * 4 + 1] = h4.y + acc[n * 4 + 1] + bb[1];
            pre[n * 4 + 2] = h4.z + acc[n * 4 + 2] + bb[2];
            pre[n * 4 + 3] = h4.w + acc[n * 4 + 3] + bb[3];
        }
    }
    float4 gv = *(const float4*)&lng[cg * 4];
    float4 bv = *(const float4*)&lnb[cg * 4];
    float hn[16];
#pragma unroll
    for (int n = 0; n < 4; n++) {
        float s1 = pre[n*4] + pre[n*4+1] + pre[n*4+2] + pre[n*4+3];
        float s2 = pre[n*4]*pre[n*4] + pre[n*4+1]*pre[n*4+1]
                 + pre[n*4+2]*pre[n*4+2] + pre[n*4+3]*pre[n*4+3];
#pragma unroll
        for (int m = 1; m < 16; m <<= 1) {
            s1 += __shfl_xor_sync(0xffffffffu, s1, m);
            s2 += __shfl_xor_sync(0xffffffffu, s2, m);
        }
        float mean = s1 * (1.f / HH);
        float var  = s2 * (1.f / HH) - mean * mean;
        float inv  = rsqrtf(var + 1e-5f);
        hn[n*4+0] = (pre[n*4+0] - mean) * inv * gv.x + bv.x;
        hn[n*4+1] = (pre[n*4+1] - mean) * inv * gv.y + bv.y;
        hn[n*4+2] = (pre[n*4+2] - mean) * inv * gv.z + bv.z;
        hn[n*4+3] = (pre[n*4+3] - mean) * inv * gv.w + bv.w;
    }

    if (mode == 1) {
        // write new h; compute next-layer gate projections a/b
#pragma unroll
        for (int n = 0; n < 4; n++) {
            int node = n0 + ng * 4 + n;
            if (node < NN)
                *(float4*)&g_ah[(size_t)node * 128 + 64 + cg * 4] =
                    make_float4(hn[n*4], hn[n*4+1], hn[n*4+2], hn[n*4+3]);
        }
        __syncthreads();   // all reads of sA/sW done
#pragma unroll
        for (int n = 0; n < 4; n++)
#pragma unroll
            for (int c = 0; c < 4; c++)
                sA[cg * 4 + c][ng * 4 + n] = hn[n * 4 + c];
        STAGE_W(sW, gw1);
        __syncthreads();

        zero16(acc);
        MATVEC(sA, sW, acc);
#pragma unroll
        for (int n = 0; n < 4; n++) {
            int node = n0 + ng * 4 + n;
            if (node < NN)
                *(float4*)&g_ah[(size_t)node * 128 + cg * 4] =
                    make_float4(acc[n*4], acc[n*4+1], acc[n*4+2], acc[n*4+3]);
        }
        __syncthreads();
        STAGE_W(sW, gw1 + (size_t)64 * HH);
        __syncthreads();

        zero16(acc);
        MATVEC(sA, sW, acc);
        float4 gbv = *(const float4*)&gb1[cg * 4];
        float gb[4] = {gbv.x, gbv.y, gbv.z, gbv.w};
#pragma unroll
        for (int n = 0; n < 4; n++) {
            int node = n0 + ng * 4 + n;
            if (node < NN)
                *(float4*)&g_b[(size_t)node * HH + cg * 4] =
                    make_float4(acc[n*4] + gb[0], acc[n*4+1] + gb[1],
                                acc[n*4+2] + gb[2], acc[n*4+3] + gb[3]);
        }
    } else {
        // fused head: U = softplus(h @ toU_w + toU_b)
        __syncthreads();   // all reads of sA/sW done
#pragma unroll
        for (int n = 0; n < 4; n++)
#pragma unroll
            for (int c = 0; c < 4; c++)
                sA[cg * 4 + c][ng * 4 + n] = hn[n * 4 + c];
        // stage toU_w (64 x 32) into sW[:, 0:32]
#pragma unroll
        for (int q = 0; q < 2; q++) {
            int lin = q * 256 + tid;
            int row = lin >> 3, c4 = (lin & 7) * 4;
            *(float4*)&sW[row][c4] = *(const float4*)&tw[row * KK + c4];
        }
        __syncthreads();

        int cg2 = tid & 7, ng2 = tid >> 3;   // 8 col-groups x 32 node-groups
        float a8[8];
#pragma unroll
        for (int k = 0; k < 8; k++) a8[k] = 0.f;
#pragma unroll 8
        for (int i = 0; i < 64; i++) {
            float2 a2 = *(float2*)&sA[i][ng2 * 2];
            float4 w4 = *(float4*)&sW[i][cg2 * 4];
            a8[0] = fmaf(a2.x, w4.x, a8[0]); a8[1] = fmaf(a2.x, w4.y, a8[1]);
            a8[2] = fmaf(a2.x, w4.z, a8[2]); a8[3] = fmaf(a2.x, w4.w, a8[3]);
            a8[4] = fmaf(a2.y, w4.x, a8[4]); a8[5] = fmaf(a2.y, w4.y, a8[5]);
            a8[6] = fmaf(a2.y, w4.z, a8[6]); a8[7] = fmaf(a2.y, w4.w, a8[7]);
        }
        float4 tb4 = *(const float4*)&tb[cg2 * 4];
        float tbb[4] = {tb4.x, tb4.y, tb4.z, tb4.w};
#pragma unroll
        for (int n = 0; n < 2; n++) {
            int node = n0 + ng2 * 2 + n;
            if (node < NN) {
                float4 o;
                float v0 = a8[n*4+0] + tbb[0];
                float v1 = a8[n*4+1] + tbb[1];
                float v2 = a8[n*4+2] + tbb[2];
                float v3 = a8[n*4+3] + tbb[3];
                o.x = log1pf(__expf(-fabsf(v0))) + fmaxf(v0, 0.f);
                o.y = log1pf(__expf(-fabsf(v1))) + fmaxf(v1, 0.f);
                o.z = log1pf(__expf(-fabsf(v2))) + fmaxf(v2, 0.f);
                o.w = log1pf(__expf(-fabsf(v3))) + fmaxf(v3, 0.f);
                *(float4*)&out[(size_t)node * KK + cg2 * 4] = o;
            }
        }
    }
}

// =====================================================================
extern "C" void kernel_launch(void* const* d_in, const int* in_sizes, int n_in,
                              void* d_out, int out_size) {
    const float* x      = (const float*)d_in[0];
    const int*   src    = (const int*)  d_in[1];
    const int*   dst    = (const int*)  d_in[2];
    const float* basew  = (const float*)d_in[3];
    const float* enc_w1 = (const float*)d_in[4];
    const float* enc_b1 = (const float*)d_in[5];
    const float* enc_w2 = (const float*)d_in[6];
    const float* enc_b2 = (const float*)d_in[7];
    const float* gw1    = (const float*)d_in[8];
    const float* gb1    = (const float*)d_in[9];
    const float* gw2    = (const float*)d_in[10];
    const float* gb2    = (const float*)d_in[11];
    const float* uw1    = (const float*)d_in[12];
    const float* ub1    = (const float*)d_in[13];
    const float* uw2    = (const float*)d_in[14];
    const float* ub2    = (const float*)d_in[15];
    const float* lng    = (const float*)d_in[16];
    const float* lnb    = (const float*)d_in[17];
    const float* rho    = (const float*)d_in[18];
    const float* tw     = (const float*)d_in[19];
    const float* tb     = (const float*)d_in[20];
    float* out = (float*)d_out;

    int nblocks = (NN + NB - 1) / NB;
    k_encoder<<<nblocks, 256>>>(x, enc_w1, enc_b1, enc_w2, enc_b2, gw1, gb1);
    k_w0<<<(EE + 255) / 256, 256>>>(src, dst, basew, rho);

    for (int l = 0; l < LL; l++) {
        k_edge<<<EE / 32, 256>>>(gw2, gb2);
        k_update<<<nblocks, 256>>>(uw1 + l * HH * HH, ub1 + l * HH,
                                   uw2 + l * HH * HH, ub2 + l * HH,
                                   lng + l * HH, lnb + l * HH,
                                   gw1, gb1, tw, tb, out,
                                   l < LL - 1 ? 1 : 0);
    }
}